// round 7
// baseline (speedup 1.0000x reference)
#include <cuda_runtime.h>

#define N_PTS   4096
#define PAIRS   8
#define TPB     256
#define J_TILE  512
#define JP_TILE (J_TILE / 2)              // 256 j-pairs per tile
#define I_TILE  512                       // 2 i-points per thread
#define J_SPLITS (N_PTS / J_TILE)         // 8
#define I_GROUPS (N_PTS / I_TILE)         // 8
#define T_DIM   4
#define INV_SCALE (1.0f / (T_DIM * N_PTS))
#define FINF    3.0e38f

// Partial (na2 + min over j-chunk) per (pair, i, jsplit): [8][4096][8] floats = 1 MB
__device__ float4 g_part4[PAIRS * N_PTS * 2];

typedef unsigned long long u64;

__device__ __forceinline__ u64 pk(float lo, float hi) {
    return ((u64)__float_as_uint(hi) << 32) | (u64)__float_as_uint(lo);
}
__device__ __forceinline__ float flo(u64 v) { return __uint_as_float((unsigned)v); }
__device__ __forceinline__ float fhi(u64 v) { return __uint_as_float((unsigned)(v >> 32)); }

__device__ __forceinline__ u64 fma2(u64 a, u64 b, u64 c) {
    u64 d;
    asm("fma.rn.f32x2 %0, %1, %2, %3;" : "=l"(d) : "l"(a), "l"(b), "l"(c));
    return d;
}

__global__ __launch_bounds__(TPB)
void hd_nn_kernel(const float* __restrict__ d1,
                  const float* __restrict__ d2) {
    // Per j-pair: sA = (bx0,bx1 | by0,by1), sB = (bz0,bz1 | w0,w1)  -> 8 KB
    __shared__ ulonglong2 sA[JP_TILE];
    __shared__ ulonglong2 sB[JP_TILE];

    const int jsplit = blockIdx.x;
    const int ibase  = blockIdx.y * I_TILE;
    const int pair   = blockIdx.z;
    const int jbase  = jsplit * J_TILE;

    // Stage: each thread packs one j-pair (6 contiguous floats)
    {
        const float2* f2 = (const float2*)(d2 + ((size_t)pair * N_PTS + jbase) * 3);
        const int jp = threadIdx.x;                  // 0..255 exactly covers tile
        float2 a = f2[3 * jp + 0];                   // bx0, by0
        float2 b = f2[3 * jp + 1];                   // bz0, bx1
        float2 c = f2[3 * jp + 2];                   // by1, bz1
        float w0 = fmaf(a.x, a.x, fmaf(a.y, a.y, b.x * b.x));
        float w1 = fmaf(b.y, b.y, fmaf(c.x, c.x, c.y * c.y));
        sA[jp] = make_ulonglong2(pk(a.x, b.y), pk(a.y, c.x));
        sB[jp] = make_ulonglong2(pk(b.x, c.y), pk(w0, w1));
    }
    __syncthreads();

    // Two set-1 points per thread; coefs packed (broadcast to both halves)
    const int i0 = ibase + threadIdx.x;
    const int i1 = i0 + TPB;
    const float* pa0 = d1 + ((size_t)pair * N_PTS + i0) * 3;
    const float* pa1 = d1 + ((size_t)pair * N_PTS + i1) * 3;
    const float a0x = pa0[0], a0y = pa0[1], a0z = pa0[2];
    const float a1x = pa1[0], a1y = pa1[1], a1z = pa1[2];
    const float na0 = fmaf(a0x, a0x, fmaf(a0y, a0y, a0z * a0z));
    const float na1 = fmaf(a1x, a1x, fmaf(a1y, a1y, a1z * a1z));
    const u64 ax0p = pk(-2.0f * a0x, -2.0f * a0x);
    const u64 ay0p = pk(-2.0f * a0y, -2.0f * a0y);
    const u64 az0p = pk(-2.0f * a0z, -2.0f * a0z);
    const u64 ax1p = pk(-2.0f * a1x, -2.0f * a1x);
    const u64 ay1p = pk(-2.0f * a1y, -2.0f * a1y);
    const u64 az1p = pk(-2.0f * a1z, -2.0f * a1z);

    float m00 = FINF, m01 = FINF;    // point i0: lo/hi chains
    float m10 = FINF, m11 = FINF;    // point i1

    #pragma unroll 4
    for (int jp = 0; jp < JP_TILE; ++jp) {
        ulonglong2 qA = sA[jp];      // (bx pair, by pair)
        ulonglong2 qB = sB[jp];      // (bz pair, w pair)

        u64 t0 = fma2(ax0p, qA.x, qB.y);
        u64 t1 = fma2(ax1p, qA.x, qB.y);
        t0 = fma2(ay0p, qA.y, t0);
        t1 = fma2(ay1p, qA.y, t1);
        t0 = fma2(az0p, qB.x, t0);
        t1 = fma2(az1p, qB.x, t1);

        m00 = fminf(m00, flo(t0));
        m01 = fminf(m01, fhi(t0));
        m10 = fminf(m10, flo(t1));
        m11 = fminf(m11, fhi(t1));
    }

    float* part = (float*)g_part4;
    part[(((size_t)pair * N_PTS + i0) << 3) + jsplit] = na0 + fminf(m00, m01);
    part[(((size_t)pair * N_PTS + i1) << 3) + jsplit] = na1 + fminf(m10, m11);
}

// One block per batch element: min over 8 partials, sqrt, sum, scale, store.
#define FTPB 512
__global__ __launch_bounds__(FTPB)
void hd_final(float* __restrict__ out) {
    __shared__ float red[FTPB / 32];
    const int b = blockIdx.x;                       // 0..1
    const size_t ebase = (size_t)b * 4 * N_PTS;     // 4 pairs per batch

    float acc = 0.0f;
    for (int k = threadIdx.x; k < 4 * N_PTS; k += FTPB) {
        size_t e = ebase + k;
        float4 p0 = g_part4[2 * e + 0];
        float4 p1 = g_part4[2 * e + 1];
        float m = fminf(fminf(fminf(p0.x, p0.y), fminf(p0.z, p0.w)),
                        fminf(fminf(p1.x, p1.y), fminf(p1.z, p1.w)));
        acc += sqrtf(fmaxf(m, 0.0f));
    }

    #pragma unroll
    for (int off = 16; off > 0; off >>= 1)
        acc += __shfl_xor_sync(0xFFFFFFFFu, acc, off);

    const int lane = threadIdx.x & 31;
    const int wid  = threadIdx.x >> 5;
    if (lane == 0) red[wid] = acc;
    __syncthreads();

    if (wid == 0) {
        float v = (lane < FTPB / 32) ? red[lane] : 0.0f;
        #pragma unroll
        for (int off = 8; off > 0; off >>= 1)
            v += __shfl_xor_sync(0xFFFFFFFFu, v, off);
        if (lane == 0)
            out[b] = v * INV_SCALE;
    }
}

extern "C" void kernel_launch(void* const* d_in, const int* in_sizes, int n_in,
                              void* d_out, int out_size) {
    const float* d1 = (const float*)d_in[0];
    const float* d2 = (const float*)d_in[1];
    float* out = (float*)d_out;

    dim3 grid(J_SPLITS, I_GROUPS, PAIRS);
    hd_nn_kernel<<<grid, TPB>>>(d1, d2);
    hd_final<<<2, FTPB>>>(out);
}

// round 8
// speedup vs baseline: 1.2998x; 1.2998x over previous
#include <cuda_runtime.h>

#define N_PTS   4096
#define PAIRS   8
#define TPB     256
#define J_TILE  512
#define JP_TILE (J_TILE / 2)              // 256 j-pairs per tile
#define I_TILE  512                       // 2 i-points per thread
#define J_SPLITS (N_PTS / J_TILE)         // 8
#define I_GROUPS (N_PTS / I_TILE)         // 8
#define T_DIM   4
#define INV_SCALE (1.0f / (T_DIM * N_PTS))
#define FINF    3.0e38f

// Partial (na2 + min over j-chunk) per (pair, i, jsplit): [8][4096][8] floats = 1 MB
__device__ float4 g_part4[PAIRS * N_PTS * 2];

typedef unsigned long long u64;

__device__ __forceinline__ u64 pk(float lo, float hi) {
    return ((u64)__float_as_uint(hi) << 32) | (u64)__float_as_uint(lo);
}
__device__ __forceinline__ float flo(u64 v) { return __uint_as_float((unsigned)v); }
__device__ __forceinline__ float fhi(u64 v) { return __uint_as_float((unsigned)(v >> 32)); }

__device__ __forceinline__ u64 fma2(u64 a, u64 b, u64 c) {
    u64 d;
    asm("fma.rn.f32x2 %0, %1, %2, %3;" : "=l"(d) : "l"(a), "l"(b), "l"(c));
    return d;
}

__global__ __launch_bounds__(TPB)
void hd_nn_kernel(const float* __restrict__ d1,
                  const float* __restrict__ d2,
                  float* __restrict__ out) {
    // Per j-pair: sA = (bx0,bx1 | by0,by1), sB = (bz0,bz1 | w0,w1)  -> 8 KB
    __shared__ ulonglong2 sA[JP_TILE];
    __shared__ ulonglong2 sB[JP_TILE];

    const int jsplit = blockIdx.x;
    const int ibase  = blockIdx.y * I_TILE;
    const int pair   = blockIdx.z;
    const int jbase  = jsplit * J_TILE;

    // Zero the output accumulators (visible to hd_final via kernel boundary)
    if (jsplit == 0 && blockIdx.y == 0 && pair == 0 && threadIdx.x < 2)
        out[threadIdx.x] = 0.0f;

    // Stage: each thread packs one j-pair (6 contiguous floats)
    {
        const float2* f2 = (const float2*)(d2 + ((size_t)pair * N_PTS + jbase) * 3);
        const int jp = threadIdx.x;                  // 0..255 exactly covers tile
        float2 a = f2[3 * jp + 0];                   // bx0, by0
        float2 b = f2[3 * jp + 1];                   // bz0, bx1
        float2 c = f2[3 * jp + 2];                   // by1, bz1
        float w0 = fmaf(a.x, a.x, fmaf(a.y, a.y, b.x * b.x));
        float w1 = fmaf(b.y, b.y, fmaf(c.x, c.x, c.y * c.y));
        sA[jp] = make_ulonglong2(pk(a.x, b.y), pk(a.y, c.x));
        sB[jp] = make_ulonglong2(pk(b.x, c.y), pk(w0, w1));
    }
    __syncthreads();

    // Two set-1 points per thread; coefs packed (broadcast to both halves)
    const int i0 = ibase + threadIdx.x;
    const int i1 = i0 + TPB;
    const float* pa0 = d1 + ((size_t)pair * N_PTS + i0) * 3;
    const float* pa1 = d1 + ((size_t)pair * N_PTS + i1) * 3;
    const float a0x = pa0[0], a0y = pa0[1], a0z = pa0[2];
    const float a1x = pa1[0], a1y = pa1[1], a1z = pa1[2];
    const float na0 = fmaf(a0x, a0x, fmaf(a0y, a0y, a0z * a0z));
    const float na1 = fmaf(a1x, a1x, fmaf(a1y, a1y, a1z * a1z));
    const u64 ax0p = pk(-2.0f * a0x, -2.0f * a0x);
    const u64 ay0p = pk(-2.0f * a0y, -2.0f * a0y);
    const u64 az0p = pk(-2.0f * a0z, -2.0f * a0z);
    const u64 ax1p = pk(-2.0f * a1x, -2.0f * a1x);
    const u64 ay1p = pk(-2.0f * a1y, -2.0f * a1y);
    const u64 az1p = pk(-2.0f * a1z, -2.0f * a1z);

    float m00 = FINF, m01 = FINF;    // point i0: lo/hi chains
    float m10 = FINF, m11 = FINF;    // point i1

    #pragma unroll 4
    for (int jp = 0; jp < JP_TILE; ++jp) {
        ulonglong2 qA = sA[jp];      // (bx pair, by pair)
        ulonglong2 qB = sB[jp];      // (bz pair, w pair)

        u64 t0 = fma2(ax0p, qA.x, qB.y);
        u64 t1 = fma2(ax1p, qA.x, qB.y);
        t0 = fma2(ay0p, qA.y, t0);
        t1 = fma2(ay1p, qA.y, t1);
        t0 = fma2(az0p, qB.x, t0);
        t1 = fma2(az1p, qB.x, t1);

        m00 = fminf(m00, flo(t0));
        m01 = fminf(m01, fhi(t0));
        m10 = fminf(m10, flo(t1));
        m11 = fminf(m11, fhi(t1));
    }

    float* part = (float*)g_part4;
    part[(((size_t)pair * N_PTS + i0) << 3) + jsplit] = na0 + fminf(m00, m01);
    part[(((size_t)pair * N_PTS + i1) << 3) + jsplit] = na1 + fminf(m10, m11);
}

// 128 blocks: each handles 256 i-points of one pair (one element per thread),
// then one atomicAdd per block into out[b].
#define FBLOCKS_PER_PAIR 16
__global__ __launch_bounds__(TPB)
void hd_final(float* __restrict__ out) {
    __shared__ float red[TPB / 32];
    const int pair  = blockIdx.x / FBLOCKS_PER_PAIR;
    const int chunk = blockIdx.x % FBLOCKS_PER_PAIR;
    const size_t e  = (size_t)pair * N_PTS + chunk * TPB + threadIdx.x;

    float4 p0 = g_part4[2 * e + 0];
    float4 p1 = g_part4[2 * e + 1];
    float m = fminf(fminf(fminf(p0.x, p0.y), fminf(p0.z, p0.w)),
                    fminf(fminf(p1.x, p1.y), fminf(p1.z, p1.w)));
    float acc = sqrtf(fmaxf(m, 0.0f));

    #pragma unroll
    for (int off = 16; off > 0; off >>= 1)
        acc += __shfl_xor_sync(0xFFFFFFFFu, acc, off);

    const int lane = threadIdx.x & 31;
    const int wid  = threadIdx.x >> 5;
    if (lane == 0) red[wid] = acc;
    __syncthreads();

    if (wid == 0) {
        float v = (lane < TPB / 32) ? red[lane] : 0.0f;
        #pragma unroll
        for (int off = 4; off > 0; off >>= 1)
            v += __shfl_xor_sync(0xFFFFFFFFu, v, off);
        if (lane == 0)
            atomicAdd(&out[pair >> 2], v * INV_SCALE);
    }
}

extern "C" void kernel_launch(void* const* d_in, const int* in_sizes, int n_in,
                              void* d_out, int out_size) {
    const float* d1 = (const float*)d_in[0];
    const float* d2 = (const float*)d_in[1];
    float* out = (float*)d_out;

    dim3 grid(J_SPLITS, I_GROUPS, PAIRS);
    hd_nn_kernel<<<grid, TPB>>>(d1, d2, out);
    hd_final<<<PAIRS * FBLOCKS_PER_PAIR, TPB>>>(out);
}